// round 7
// baseline (speedup 1.0000x reference)
#include <cuda_runtime.h>
#include <math.h>

#define E 2048
#define NBLK 148
#define NTHR 256
#define NWARPS (NBLK * 8)
#define NSLAB 37
#define SLABSZ 56

typedef unsigned long long ull;

// ---------------- static scratch ----------------
__device__ ull    g_PN[6 * E];            // pack(exp(e2), exp(.2 e2))
__device__ ull    g_m1[6 * E];            // pack(exp(e1), exp(.2 e1))
__device__ ull    g_m2[6 * E];            // pack(P1/R, N1/R)
__device__ ull    g_h01[6 * E];
__device__ ull    g_h23[6 * E];
__device__ ull    g_h45[6 * E];
__device__ float  g_part[NSLAB * 36 * E]; // [slab][cd][j]
__device__ float  g_XW[E * 32];
__device__ float  g_G1p[4 * E * 32];      // 4 k-slices
__device__ float4 g_Z[E];

// ---------------- grid barrier (gen-based, replay-safe) ----------------
__device__ unsigned g_gen = 0;
__device__ unsigned g_cnt = 0;

__device__ __forceinline__ void gsync() {
    __syncthreads();
    if (threadIdx.x == 0) {
        __threadfence();
        unsigned gen = atomicAdd(&g_gen, 0u);
        if (atomicAdd(&g_cnt, 1u) == NBLK - 1) {
            g_cnt = 0;
            __threadfence();
            atomicAdd(&g_gen, 1u);
        } else {
            while (atomicAdd(&g_gen, 0u) == gen) {}
        }
    }
    __syncthreads();
}

// ---------------- packed f32x2 helpers ----------------
__device__ __forceinline__ ull pack2(float x, float y) {
    ull r; asm("mov.b64 %0, {%1, %2};" : "=l"(r) : "f"(x), "f"(y)); return r;
}
__device__ __forceinline__ float2 unpack2(ull v) {
    float2 r; asm("mov.b64 {%0, %1}, %2;" : "=f"(r.x), "=f"(r.y) : "l"(v)); return r;
}
__device__ __forceinline__ void ffma2(ull& d, ull a, ull b) {
    asm("fma.rn.f32x2 %0, %1, %2, %0;" : "+l"(d) : "l"(a), "l"(b));
}
__device__ __forceinline__ ull mul2(ull a, ull b) {
    ull r; asm("mul.rn.f32x2 %0, %1, %2;" : "=l"(r) : "l"(a), "l"(b)); return r;
}

// ---------------- the persistent mega-kernel ----------------
__global__ void __launch_bounds__(NTHR) mega(
    const float* __restrict__ node, const float* __restrict__ uv,
    const float* __restrict__ adj,
    const float* __restrict__ Wt1, const float* __restrict__ at1,
    const float* __restrict__ Wt2, const float* __restrict__ at2,
    const float* __restrict__ Wg1, const float* __restrict__ bg1,
    const float* __restrict__ Wg2, const float* __restrict__ bg2,
    const float* __restrict__ Wo1, const float* __restrict__ bo1,
    const float* __restrict__ Wo2, const float* __restrict__ bo2,
    float* __restrict__ out)
{
    __shared__ float s_u[3136];
    int tid = threadIdx.x;
    int bid = blockIdx.x;
    int lane = tid & 31;
    int gwarp = bid * 8 + (tid >> 5);

    // ===== phase 1: per-node h + factor pairs =====
    for (int idx = bid * NTHR + tid; idx < 6 * E; idx += NBLK * NTHR) {
        int c = idx >> 11, i = idx & 2047;
        int g = (c >= 3);
        int t = g ? c - 3 : c;
        const float* W  = (g ? Wt2 : Wt1) + t * 192;
        const float* av = (g ? at2 : at1) + t * 12;
        const float* xr = (g ? uv : node) + i * 32;   // batch 0
        float h[6] = {0.f, 0.f, 0.f, 0.f, 0.f, 0.f};
#pragma unroll
        for (int k = 0; k < 32; k++) {
            float xk = __ldg(&xr[k]);
#pragma unroll
            for (int d = 0; d < 6; d++) h[d] = fmaf(xk, __ldg(&W[k * 6 + d]), h[d]);
        }
        float e1 = 0.f, e2 = 0.f;
#pragma unroll
        for (int d = 0; d < 6; d++) {
            e1 = fmaf(h[d], __ldg(&av[d]), e1);
            e2 = fmaf(h[d], __ldg(&av[6 + d]), e2);
        }
        int gi = c * E + i;
        g_m1[gi]  = pack2(__expf(e1), __expf(0.2f * e1));
        g_PN[gi]  = pack2(__expf(e2), __expf(0.2f * e2));
        g_h01[gi] = pack2(h[0], h[1]);
        g_h23[gi] = pack2(h[2], h[3]);
        g_h45[gi] = pack2(h[4], h[5]);
    }
    gsync();

    // ===== phase 2: softmax row denominators (warp per row) =====
    for (int r = gwarp; r < E; r += NWARPS) {
        ull mk[6]; float acc[6];
#pragma unroll
        for (int c = 0; c < 6; c++) { mk[c] = g_m1[c * E + r]; acc[c] = 0.f; }
        const float* arow = &adj[(size_t)r * E];
        for (int it = 0; it < 16; it++) {
            int j = it * 128 + lane * 4;
            float4 av = *(const float4*)&arow[j];
#pragma unroll
            for (int c = 0; c < 6; c++) {
                ulonglong2 pn01 = *(const ulonglong2*)&g_PN[c * E + j];
                ulonglong2 pn23 = *(const ulonglong2*)&g_PN[c * E + j + 2];
                float2 t;
                t = unpack2(mul2(mk[c], pn01.x)); acc[c] = fmaf(av.x, fmaxf(t.x, t.y), acc[c]);
                t = unpack2(mul2(mk[c], pn01.y)); acc[c] = fmaf(av.y, fmaxf(t.x, t.y), acc[c]);
                t = unpack2(mul2(mk[c], pn23.x)); acc[c] = fmaf(av.z, fmaxf(t.x, t.y), acc[c]);
                t = unpack2(mul2(mk[c], pn23.y)); acc[c] = fmaf(av.w, fmaxf(t.x, t.y), acc[c]);
            }
        }
#pragma unroll
        for (int c = 0; c < 6; c++) {
            float v = acc[c];
            for (int off = 16; off; off >>= 1) v += __shfl_down_sync(0xffffffffu, v, off);
            if (lane == 0) {
                float inv = 1.0f / v;
                float2 m = unpack2(mk[c]);
                g_m2[c * E + r] = pack2(m.x * inv, m.y * inv);
            }
        }
    }
    gsync();

    // ===== phase 3: attention aggregation (3552 warp-tasks, 3 per warp) =====
    for (int task = gwarp; task < 96 * NSLAB; task += NWARPS) {
        int c    = task % 6;
        int jt   = (task / 6) % 16;
        int slab = task / 96;
        int j0 = jt * 128 + lane * 4;
        int ib = slab * SLABSZ;
        int iend = ib + SLABSZ; if (iend > E) iend = E;

        ull PN[4];
#pragma unroll
        for (int q = 0; q < 4; q++) PN[q] = __ldg(&g_PN[c * E + j0 + q]);

        ull acc[12];
#pragma unroll
        for (int q = 0; q < 12; q++) acc[q] = 0;

#pragma unroll 1
        for (int ii = ib; ii < iend; ii += 4) {
            float4 av[4];
#pragma unroll
            for (int u = 0; u < 4; u++)
                av[u] = *(const float4*)&adj[(size_t)(ii + u) * E + j0];
#pragma unroll
            for (int u = 0; u < 4; u++) {
                int i = ii + u;
                ull pk  = __ldg(&g_m2[c * E + i]);
                ull h01 = __ldg(&g_h01[c * E + i]);
                ull h23 = __ldg(&g_h23[c * E + i]);
                ull h45 = __ldg(&g_h45[c * E + i]);
                const float* af = (const float*)&av[u];
#pragma unroll
                for (int q = 0; q < 4; q++) {
                    float2 t = unpack2(mul2(pk, PN[q]));
                    float w = fmaxf(t.x, t.y) * af[q];
                    ull wp = pack2(w, w);
                    ffma2(acc[q * 3 + 0], wp, h01);
                    ffma2(acc[q * 3 + 1], wp, h23);
                    ffma2(acc[q * 3 + 2], wp, h45);
                }
            }
        }

        int base = slab * 36 + c * 6;
#pragma unroll
        for (int p = 0; p < 3; p++) {
            float2 t0 = unpack2(acc[p]), t1 = unpack2(acc[3 + p]);
            float2 t2 = unpack2(acc[6 + p]), t3 = unpack2(acc[9 + p]);
            *(float4*)&g_part[(size_t)(base + 2 * p) * E + j0] =
                make_float4(t0.x, t1.x, t2.x, t3.x);
            *(float4*)&g_part[(size_t)(base + 2 * p + 1) * E + j0] =
                make_float4(t0.y, t1.y, t2.y, t3.y);
        }
    }
    gsync();

    // ===== phase 4: slab-reduce + ELU + XW  (64 tiles) =====
    for (int tile = bid; tile < 64; tile += NBLK) {
        int j0 = tile * 32;
        float* sh = s_u;              // [36][33]
        float* sW0 = s_u + 1188;      // 288
        float* sW1 = s_u + 1476;      // 288
        for (int t = tid; t < 288; t += NTHR) {
            sW0[t] = __ldg(&Wg1[t]);
            sW1[t] = __ldg(&Wo1[t]);
        }
        for (int t = tid; t < 36 * 32; t += NTHR) {
            int cd = t >> 5, jj = t & 31;
            int j = j0 + jj;
            float s = 0.f;
            for (int sl = 0; sl < NSLAB; sl++)
                s += g_part[(size_t)(sl * 36 + cd) * E + j];
            sh[cd * 33 + jj] = s > 0.f ? s : expm1f(s);
        }
        __syncthreads();
        for (int o = tid; o < 1024; o += NTHR) {
            int c = o >> 5, jj = o & 31;
            int g = c >> 4, cc = c & 15;
            const float* sW = g ? sW1 : sW0;
            float s = 0.f;
#pragma unroll
            for (int k = 0; k < 18; k++)
                s = fmaf(sh[(g * 18 + k) * 33 + jj], sW[k * 16 + cc], s);
            g_XW[(j0 + jj) * 32 + c] = s;
        }
        __syncthreads();
    }
    gsync();

    // ===== phase 5: a0 @ XW  (128 block-tasks: 32 r-tiles x 4 k-slices) =====
    for (int task = bid; task < 128; task += NBLK) {
        int r0 = (task & 31) * 64;
        int ks = task >> 5;
        float* As = s_u;              // [64][33]
        float* Bs = s_u + 2112;       // [32][32]
        int rl = tid >> 2, cg = (tid & 3) * 8;
        int kc = tid & 31, rr = tid >> 5;
        float acc[8];
#pragma unroll
        for (int u = 0; u < 8; u++) acc[u] = 0.f;

        for (int kt = 0; kt < 16; kt++) {
            int kb = ks * 512 + kt * 32;
            __syncthreads();
#pragma unroll
            for (int p = 0; p < 8; p++)
                As[(rr + p * 8) * 33 + kc] = adj[(size_t)(r0 + rr + p * 8) * E + kb + kc];
#pragma unroll
            for (int p = 0; p < 4; p++)
                Bs[(rr + p * 8) * 32 + kc] = g_XW[(kb + rr + p * 8) * 32 + kc];
            __syncthreads();
#pragma unroll
            for (int kk = 0; kk < 32; kk++) {
                float a = As[rl * 33 + kk];
                const float4* b = (const float4*)&Bs[kk * 32 + cg];
                float4 b0 = b[0], b1 = b[1];
                acc[0] = fmaf(a, b0.x, acc[0]);
                acc[1] = fmaf(a, b0.y, acc[1]);
                acc[2] = fmaf(a, b0.z, acc[2]);
                acc[3] = fmaf(a, b0.w, acc[3]);
                acc[4] = fmaf(a, b1.x, acc[4]);
                acc[5] = fmaf(a, b1.y, acc[5]);
                acc[6] = fmaf(a, b1.z, acc[6]);
                acc[7] = fmaf(a, b1.w, acc[7]);
            }
        }
        float* dst = &g_G1p[((size_t)ks * E + r0 + rl) * 32 + cg];
        ((float4*)dst)[0] = make_float4(acc[0], acc[1], acc[2], acc[3]);
        ((float4*)dst)[1] = make_float4(acc[4], acc[5], acc[6], acc[7]);
        __syncthreads();
    }
    gsync();

    // ===== phase 6: k-slice reduce + bias/relu + layer-2 weights =====
    for (int j = bid * NTHR + tid; j < E; j += NBLK * NTHR) {
        float y[32];
#pragma unroll
        for (int c4 = 0; c4 < 8; c4++) {
            float4 s = make_float4(0.f, 0.f, 0.f, 0.f);
#pragma unroll
            for (int ks = 0; ks < 4; ks++) {
                float4 v = *(const float4*)&g_G1p[((size_t)ks * E + j) * 32 + c4 * 4];
                s.x += v.x; s.y += v.y; s.z += v.z; s.w += v.w;
            }
            y[c4 * 4 + 0] = s.x; y[c4 * 4 + 1] = s.y;
            y[c4 * 4 + 2] = s.z; y[c4 * 4 + 3] = s.w;
        }
#pragma unroll
        for (int c = 0; c < 16; c++) {
            float a = y[c] + __ldg(&bg1[c]);
            y[c] = a > 0.f ? a : 0.f;
            float b = y[16 + c] + __ldg(&bo1[c]);
            y[16 + c] = b > 0.f ? b : 0.f;
        }
        float z0 = 0.f, z1 = 0.f, z2 = 0.f, z3 = 0.f;
#pragma unroll
        for (int k = 0; k < 16; k++) {
            z0 = fmaf(y[k], __ldg(&Wg2[k * 2 + 0]), z0);
            z1 = fmaf(y[k], __ldg(&Wg2[k * 2 + 1]), z1);
            z2 = fmaf(y[16 + k], __ldg(&Wo2[k * 2 + 0]), z2);
            z3 = fmaf(y[16 + k], __ldg(&Wo2[k * 2 + 1]), z3);
        }
        g_Z[j] = make_float4(z0, z1, z2, z3);
    }
    gsync();

    // ===== phase 7: a0 @ Z + bias, log_softmax / leaky (warp per row) =====
    for (int r = gwarp; r < E; r += NWARPS) {
        float a0 = 0.f, a1 = 0.f, a2 = 0.f, a3 = 0.f;
        for (int q = 0; q < 64; q++) {
            int k = q * 32 + lane;
            float av = adj[(size_t)r * E + k];
            float4 z = g_Z[k];
            a0 = fmaf(av, z.x, a0);
            a1 = fmaf(av, z.y, a1);
            a2 = fmaf(av, z.z, a2);
            a3 = fmaf(av, z.w, a3);
        }
        for (int off = 16; off; off >>= 1) {
            a0 += __shfl_down_sync(0xffffffffu, a0, off);
            a1 += __shfl_down_sync(0xffffffffu, a1, off);
            a2 += __shfl_down_sync(0xffffffffu, a2, off);
            a3 += __shfl_down_sync(0xffffffffu, a3, off);
        }
        if (lane == 0) {
            float y0 = a0 + __ldg(&bg2[0]), y1 = a1 + __ldg(&bg2[1]);
            float m = fmaxf(y0, y1);
            float l = m + logf(expf(y0 - m) + expf(y1 - m));
            out[r * 2 + 0] = y0 - l;
            out[r * 2 + 1] = y1 - l;
            float o0 = a2 + __ldg(&bo2[0]), o1 = a3 + __ldg(&bo2[1]);
            out[2 * E + r * 2 + 0] = o0 > 0.f ? o0 : 0.01f * o0;
            out[2 * E + r * 2 + 1] = o1 > 0.f ? o1 : 0.01f * o1;
        }
    }
}

// ---------------- launch ----------------
extern "C" void kernel_launch(void* const* d_in, const int* in_sizes, int n_in,
                              void* d_out, int out_size)
{
    (void)in_sizes; (void)n_in; (void)out_size;
    mega<<<NBLK, NTHR>>>(
        (const float*)d_in[0], (const float*)d_in[1], (const float*)d_in[2],
        (const float*)d_in[3], (const float*)d_in[4],
        (const float*)d_in[5], (const float*)d_in[6],
        (const float*)d_in[7], (const float*)d_in[8],
        (const float*)d_in[9], (const float*)d_in[10],
        (const float*)d_in[11], (const float*)d_in[12],
        (const float*)d_in[13], (const float*)d_in[14],
        (float*)d_out);
}

// round 9
// speedup vs baseline: 1.1949x; 1.1949x over previous
#include <cuda_runtime.h>
#include <math.h>

#define E 2048
#define NBLK 444
#define NTHR 256
#define NWARPS (NBLK * 8)
#define NSLAB 37
#define SLABSZ 56

typedef unsigned long long ull;

// ---------------- static scratch ----------------
__device__ ull    g_PN[6 * E];            // pack(exp(e2), exp(.2 e2))
__device__ ull    g_m1[6 * E];            // pack(exp(e1), exp(.2 e1))
__device__ ull    g_m2[6 * E];            // pack(P1/R, N1/R)
__device__ ull    g_h01[6 * E];
__device__ ull    g_h23[6 * E];
__device__ ull    g_h45[6 * E];
__device__ float  g_part[NSLAB * 36 * E]; // [slab][cd][j]
__device__ float  g_XW[E * 32];
__device__ float  g_G1p[8 * E * 32];      // 8 k-slices
__device__ float4 g_Z[E];

// ---------------- grid barrier (spread counters, monotone, replay-safe) ----------------
__device__ unsigned g_cnt16[16 * 32];     // arrival counters, 128B apart
__device__ unsigned g_rel;                // total releases ever (monotone)

__device__ __forceinline__ void gsync(unsigned base, unsigned epoch) {
    __syncthreads();
    if (threadIdx.x == 0) {
        __threadfence();
        atomicAdd(&g_cnt16[(blockIdx.x & 15) * 32], 1u);
        if (blockIdx.x == 0) {
            unsigned want = (unsigned)NBLK * (base + epoch);
            unsigned s;
            do {
                s = 0;
#pragma unroll
                for (int k = 0; k < 16; k++)
                    s += *(volatile unsigned*)&g_cnt16[k * 32];
            } while (s != want);
            __threadfence();
            *(volatile unsigned*)&g_rel = base + epoch;
        } else {
            while ((*(volatile unsigned*)&g_rel) - base < epoch) __nanosleep(64);
            __threadfence();
        }
    }
    __syncthreads();
}

// ---------------- packed f32x2 helpers ----------------
__device__ __forceinline__ ull pack2(float x, float y) {
    ull r; asm("mov.b64 %0, {%1, %2};" : "=l"(r) : "f"(x), "f"(y)); return r;
}
__device__ __forceinline__ float2 unpack2(ull v) {
    float2 r; asm("mov.b64 {%0, %1}, %2;" : "=f"(r.x), "=f"(r.y) : "l"(v)); return r;
}
__device__ __forceinline__ void ffma2(ull& d, ull a, ull b) {
    asm("fma.rn.f32x2 %0, %1, %2, %0;" : "+l"(d) : "l"(a), "l"(b));
}
__device__ __forceinline__ ull mul2(ull a, ull b) {
    ull r; asm("mul.rn.f32x2 %0, %1, %2;" : "=l"(r) : "l"(a), "l"(b)); return r;
}

// ---------------- the persistent mega-kernel ----------------
__global__ void __launch_bounds__(NTHR, 3) mega(
    const float* __restrict__ node, const float* __restrict__ uv,
    const float* __restrict__ adj,
    const float* __restrict__ Wt1, const float* __restrict__ at1,
    const float* __restrict__ Wt2, const float* __restrict__ at2,
    const float* __restrict__ Wg1, const float* __restrict__ bg1,
    const float* __restrict__ Wg2, const float* __restrict__ bg2,
    const float* __restrict__ Wo1, const float* __restrict__ bo1,
    const float* __restrict__ Wo2, const float* __restrict__ bo2,
    float* __restrict__ out)
{
    __shared__ float s_u[3136];
    int tid = threadIdx.x;
    int bid = blockIdx.x;
    int lane = tid & 31;
    int gwarp = bid * 8 + (tid >> 5);
    unsigned base = *(volatile unsigned*)&g_rel;   // stable between replays

    // ===== phase 1: per-node h + factor pairs =====
    for (int idx = bid * NTHR + tid; idx < 6 * E; idx += NBLK * NTHR) {
        int c = idx >> 11, i = idx & 2047;
        int g = (c >= 3);
        int t = g ? c - 3 : c;
        const float* W  = (g ? Wt2 : Wt1) + t * 192;
        const float* av = (g ? at2 : at1) + t * 12;
        const float* xr = (g ? uv : node) + i * 32;   // batch 0
        float h[6] = {0.f, 0.f, 0.f, 0.f, 0.f, 0.f};
#pragma unroll
        for (int k = 0; k < 32; k++) {
            float xk = __ldg(&xr[k]);
#pragma unroll
            for (int d = 0; d < 6; d++) h[d] = fmaf(xk, __ldg(&W[k * 6 + d]), h[d]);
        }
        float e1 = 0.f, e2 = 0.f;
#pragma unroll
        for (int d = 0; d < 6; d++) {
            e1 = fmaf(h[d], __ldg(&av[d]), e1);
            e2 = fmaf(h[d], __ldg(&av[6 + d]), e2);
        }
        int gi = c * E + i;
        g_m1[gi]  = pack2(__expf(e1), __expf(0.2f * e1));
        g_PN[gi]  = pack2(__expf(e2), __expf(0.2f * e2));
        g_h01[gi] = pack2(h[0], h[1]);
        g_h23[gi] = pack2(h[2], h[3]);
        g_h45[gi] = pack2(h[4], h[5]);
    }
    gsync(base, 1);

    // ===== phase 2: softmax row denominators (warp per row-halfcombo) =====
    for (int task = gwarp; task < 4096; task += NWARPS) {
        int r  = task >> 1;
        int c0 = (task & 1) * 3;
        ull mk[3]; float acc[3];
#pragma unroll
        for (int cc = 0; cc < 3; cc++) { mk[cc] = g_m1[(c0 + cc) * E + r]; acc[cc] = 0.f; }
        const float* arow = &adj[(size_t)r * E];
        for (int it = 0; it < 16; it++) {
            int j = it * 128 + lane * 4;
            float4 av = *(const float4*)&arow[j];
#pragma unroll
            for (int cc = 0; cc < 3; cc++) {
                int c = c0 + cc;
                ulonglong2 pn01 = *(const ulonglong2*)&g_PN[c * E + j];
                ulonglong2 pn23 = *(const ulonglong2*)&g_PN[c * E + j + 2];
                float2 t;
                t = unpack2(mul2(mk[cc], pn01.x)); acc[cc] = fmaf(av.x, fmaxf(t.x, t.y), acc[cc]);
                t = unpack2(mul2(mk[cc], pn01.y)); acc[cc] = fmaf(av.y, fmaxf(t.x, t.y), acc[cc]);
                t = unpack2(mul2(mk[cc], pn23.x)); acc[cc] = fmaf(av.z, fmaxf(t.x, t.y), acc[cc]);
                t = unpack2(mul2(mk[cc], pn23.y)); acc[cc] = fmaf(av.w, fmaxf(t.x, t.y), acc[cc]);
            }
        }
#pragma unroll
        for (int cc = 0; cc < 3; cc++) {
            float v = acc[cc];
            for (int off = 16; off; off >>= 1) v += __shfl_down_sync(0xffffffffu, v, off);
            if (lane == 0) {
                float inv = 1.0f / v;
                float2 m = unpack2(mk[cc]);
                g_m2[(c0 + cc) * E + r] = pack2(m.x * inv, m.y * inv);
            }
        }
    }
    gsync(base, 2);

    // ===== phase 3: attention aggregation (3552 warp-tasks, 1 per warp) =====
    for (int task = gwarp; task < 96 * NSLAB; task += NWARPS) {
        int c    = task % 6;
        int jt   = (task / 6) % 16;
        int slab = task / 96;
        int j0 = jt * 128 + lane * 4;
        int ib = slab * SLABSZ;
        int iend = ib + SLABSZ; if (iend > E) iend = E;

        ull PN[4];
#pragma unroll
        for (int q = 0; q < 4; q++) PN[q] = __ldg(&g_PN[c * E + j0 + q]);

        ull acc[12];
#pragma unroll
        for (int q = 0; q < 12; q++) acc[q] = 0;

#pragma unroll 1
        for (int ii = ib; ii < iend; ii += 4) {
            float4 av[4];
#pragma unroll
            for (int u = 0; u < 4; u++)
                av[u] = *(const float4*)&adj[(size_t)(ii + u) * E + j0];
#pragma unroll
            for (int u = 0; u < 4; u++) {
                int i = ii + u;
                ull pk  = __ldg(&g_m2[c * E + i]);
                ull h01 = __ldg(&g_h01[c * E + i]);
                ull h23 = __ldg(&g_h23[c * E + i]);
                ull h45 = __ldg(&g_h45[c * E + i]);
                const float* af = (const float*)&av[u];
#pragma unroll
                for (int q = 0; q < 4; q++) {
                    float2 t = unpack2(mul2(pk, PN[q]));
                    float w = fmaxf(t.x, t.y) * af[q];
                    ull wp = pack2(w, w);
                    ffma2(acc[q * 3 + 0], wp, h01);
                    ffma2(acc[q * 3 + 1], wp, h23);
                    ffma2(acc[q * 3 + 2], wp, h45);
                }
            }
        }

        int bse = slab * 36 + c * 6;
#pragma unroll
        for (int p = 0; p < 3; p++) {
            float2 t0 = unpack2(acc[p]), t1 = unpack2(acc[3 + p]);
            float2 t2 = unpack2(acc[6 + p]), t3 = unpack2(acc[9 + p]);
            *(float4*)&g_part[(size_t)(bse + 2 * p) * E + j0] =
                make_float4(t0.x, t1.x, t2.x, t3.x);
            *(float4*)&g_part[(size_t)(bse + 2 * p + 1) * E + j0] =
                make_float4(t0.y, t1.y, t2.y, t3.y);
        }
    }
    gsync(base, 3);

    // ===== phase 4: slab-reduce + ELU + XW  (64 tiles) =====
    for (int tile = bid; tile < 64; tile += NBLK) {
        int j0 = tile * 32;
        float* sh = s_u;              // [36][33]
        float* sW0 = s_u + 1188;      // 288
        float* sW1 = s_u + 1476;      // 288
        for (int t = tid; t < 288; t += NTHR) {
            sW0[t] = __ldg(&Wg1[t]);
            sW1[t] = __ldg(&Wo1[t]);
        }
        for (int t = tid; t < 36 * 32; t += NTHR) {
            int cd = t >> 5, jj = t & 31;
            int j = j0 + jj;
            float s = 0.f;
            for (int sl = 0; sl < NSLAB; sl++)
                s += g_part[(size_t)(sl * 36 + cd) * E + j];
            sh[cd * 33 + jj] = s > 0.f ? s : expm1f(s);
        }
        __syncthreads();
        for (int o = tid; o < 1024; o += NTHR) {
            int c = o >> 5, jj = o & 31;
            int g = c >> 4, cc = c & 15;
            const float* sW = g ? sW1 : sW0;
            float s = 0.f;
#pragma unroll
            for (int k = 0; k < 18; k++)
                s = fmaf(sh[(g * 18 + k) * 33 + jj], sW[k * 16 + cc], s);
            g_XW[(j0 + jj) * 32 + c] = s;
        }
        __syncthreads();
    }
    gsync(base, 4);

    // ===== phase 5: a0 @ XW  (256 block-tasks: 32 r-tiles x 8 k-slices) =====
    for (int task = bid; task < 256; task += NBLK) {
        int r0 = (task & 31) * 64;
        int ks = task >> 5;
        float* As = s_u;              // [64][33]
        float* Bs = s_u + 2112;       // [32][32]
        int rl = tid >> 2, cg = (tid & 3) * 8;
        int kc = tid & 31, rr = tid >> 5;
        float acc[8];
#pragma unroll
        for (int u = 0; u < 8; u++) acc[u] = 0.f;

        for (int kt = 0; kt < 8; kt++) {
            int kb = ks * 256 + kt * 32;
            __syncthreads();
#pragma unroll
            for (int p = 0; p < 8; p++)
                As[(rr + p * 8) * 33 + kc] = adj[(size_t)(r0 + rr + p * 8) * E + kb + kc];
#pragma unroll
            for (int p = 0; p < 4; p++)
                Bs[(rr + p * 8) * 32 + kc] = g_XW[(kb + rr + p * 8) * 32 + kc];
            __syncthreads();
#pragma unroll
            for (int kk = 0; kk < 32; kk++) {
                float a = As[rl * 33 + kk];
                const float4* b = (const float4*)&Bs[kk * 32 + cg];
                float4 b0 = b[0], b1 = b[1];
                acc[0] = fmaf(a, b0.x, acc[0]);
                acc[1] = fmaf(a, b0.y, acc[1]);
                acc[2] = fmaf(a, b0.z, acc[2]);
                acc[3] = fmaf(a, b0.w, acc[3]);
                acc[4] = fmaf(a, b1.x, acc[4]);
                acc[5] = fmaf(a, b1.y, acc[5]);
                acc[6] = fmaf(a, b1.z, acc[6]);
                acc[7] = fmaf(a, b1.w, acc[7]);
            }
        }
        float* dst = &g_G1p[((size_t)ks * E + r0 + rl) * 32 + cg];
        ((float4*)dst)[0] = make_float4(acc[0], acc[1], acc[2], acc[3]);
        ((float4*)dst)[1] = make_float4(acc[4], acc[5], acc[6], acc[7]);
        __syncthreads();
    }
    gsync(base, 5);

    // ===== phase 6: k-slice reduce + bias/relu + layer-2 weights =====
    for (int j = bid * NTHR + tid; j < E; j += NBLK * NTHR) {
        float y[32];
#pragma unroll
        for (int c4 = 0; c4 < 8; c4++) {
            float4 s = make_float4(0.f, 0.f, 0.f, 0.f);
#pragma unroll
            for (int ks = 0; ks < 8; ks++) {
                float4 v = *(const float4*)&g_G1p[((size_t)ks * E + j) * 32 + c4 * 4];
                s.x += v.x; s.y += v.y; s.z += v.z; s.w += v.w;
            }
            y[c4 * 4 + 0] = s.x; y[c4 * 4 + 1] = s.y;
            y[c4 * 4 + 2] = s.z; y[c4 * 4 + 3] = s.w;
        }
#pragma unroll
        for (int c = 0; c < 16; c++) {
            float a = y[c] + __ldg(&bg1[c]);
            y[c] = a > 0.f ? a : 0.f;
            float b = y[16 + c] + __ldg(&bo1[c]);
            y[16 + c] = b > 0.f ? b : 0.f;
        }
        float z0 = 0.f, z1 = 0.f, z2 = 0.f, z3 = 0.f;
#pragma unroll
        for (int k = 0; k < 16; k++) {
            z0 = fmaf(y[k], __ldg(&Wg2[k * 2 + 0]), z0);
            z1 = fmaf(y[k], __ldg(&Wg2[k * 2 + 1]), z1);
            z2 = fmaf(y[16 + k], __ldg(&Wo2[k * 2 + 0]), z2);
            z3 = fmaf(y[16 + k], __ldg(&Wo2[k * 2 + 1]), z3);
        }
        g_Z[j] = make_float4(z0, z1, z2, z3);
    }
    gsync(base, 6);

    // ===== phase 7: a0 @ Z + bias, log_softmax / leaky (warp per row) =====
    for (int r = gwarp; r < E; r += NWARPS) {
        float a0 = 0.f, a1 = 0.f, a2 = 0.f, a3 = 0.f;
        for (int q = 0; q < 64; q++) {
            int k = q * 32 + lane;
            float av = adj[(size_t)r * E + k];
            float4 z = g_Z[k];
            a0 = fmaf(av, z.x, a0);
            a1 = fmaf(av, z.y, a1);
            a2 = fmaf(av, z.z, a2);
            a3 = fmaf(av, z.w, a3);
        }
        for (int off = 16; off; off >>= 1) {
            a0 += __shfl_down_sync(0xffffffffu, a0, off);
            a1 += __shfl_down_sync(0xffffffffu, a1, off);
            a2 += __shfl_down_sync(0xffffffffu, a2, off);
            a3 += __shfl_down_sync(0xffffffffu, a3, off);
        }
        if (lane == 0) {
            float y0 = a0 + __ldg(&bg2[0]), y1 = a1 + __ldg(&bg2[1]);
            float m = fmaxf(y0, y1);
            float l = m + logf(expf(y0 - m) + expf(y1 - m));
            out[r * 2 + 0] = y0 - l;
            out[r * 2 + 1] = y1 - l;
            float o0 = a2 + __ldg(&bo2[0]), o1 = a3 + __ldg(&bo2[1]);
            out[2 * E + r * 2 + 0] = o0 > 0.f ? o0 : 0.01f * o0;
            out[2 * E + r * 2 + 1] = o1 > 0.f ? o1 : 0.01f * o1;
        }
    }
}

// ---------------- launch ----------------
extern "C" void kernel_launch(void* const* d_in, const int* in_sizes, int n_in,
                              void* d_out, int out_size)
{
    (void)in_sizes; (void)n_in; (void)out_size;
    mega<<<NBLK, NTHR>>>(
        (const float*)d_in[0], (const float*)d_in[1], (const float*)d_in[2],
        (const float*)d_in[3], (const float*)d_in[4],
        (const float*)d_in[5], (const float*)d_in[6],
        (const float*)d_in[7], (const float*)d_in[8],
        (const float*)d_in[9], (const float*)d_in[10],
        (const float*)d_in[11], (const float*)d_in[12],
        (const float*)d_in[13], (const float*)d_in[14],
        (float*)d_out);
}